// round 1
// baseline (speedup 1.0000x reference)
#include <cuda_runtime.h>
#include <cuda_bf16.h>
#include <cstdint>
#include <math.h>

// ============================================================================
// NTXentLoss (B=8192, D=1024) — single-GEMM-sweep row+col softmax stats.
// loss = 0.5*(mean_rows(LSE'_row - diag) + mean_cols(LSE'_col - diag))
// LSE' corrects for scaling the hard-negative (off-diag max) logit by 1.5.
// ============================================================================

#define NB 8192
#define ND 1024
#define BM 64
#define BN 128
#define BK 64
#define NTHREADS 128
#define LDA_S (ND + 8)   // 1032 elements: +16B/row to dodge ldmatrix conflicts
#define LDB_S (BK + 8)   // 72
#define NJT (NB / BN)    // 64 j-tiles
#define NKC (ND / BK)    // 16 k-chunks
#define NBLK (NB / BM)   // 128 blocks
#define TEMP_INV 20.0f   // 1/0.05, folded into image at conversion
#define HNW 1.5f         // 1 + hard_negative_weight

// Static device scratch (allocation-free rule)
__device__ __nv_bfloat16 g_a[(size_t)NB * ND];  // image * 20  (bf16)
__device__ __nv_bfloat16 g_b[(size_t)NB * ND];  // song        (bf16)
__device__ float g_pm[(size_t)NBLK * NB];       // per-(block,col) partial max
__device__ float g_ps[(size_t)NBLK * NB];       // partial expsum
__device__ float g_pv[(size_t)NBLK * NB];       // partial offdiag max
__device__ float g_pd[(size_t)NBLK * NB];       // partial diag (-inf if absent)
__device__ double g_acc[2];                     // [0]=i2s row losses, [1]=s2i

// ----------------------------------------------------------------------------
__global__ void convert_kernel(const float* __restrict__ img,
                               const float* __restrict__ song) {
    size_t i = (size_t)blockIdx.x * blockDim.x + threadIdx.x;
    if (i == 0) { g_acc[0] = 0.0; g_acc[1] = 0.0; }
    size_t idx = i * 4;
    if (idx < (size_t)NB * ND) {
        float4 a = *(const float4*)(img + idx);
        float4 b = *(const float4*)(song + idx);
        *(__nv_bfloat162*)(g_a + idx)     = __floats2bfloat162_rn(a.x * TEMP_INV, a.y * TEMP_INV);
        *(__nv_bfloat162*)(g_a + idx + 2) = __floats2bfloat162_rn(a.z * TEMP_INV, a.w * TEMP_INV);
        *(__nv_bfloat162*)(g_b + idx)     = __floats2bfloat162_rn(b.x, b.y);
        *(__nv_bfloat162*)(g_b + idx + 2) = __floats2bfloat162_rn(b.z, b.w);
    }
}

// ----------------------------------------------------------------------------
// GEMM + stats: block = 64 rows (A resident in smem, full K), sweeps 64 tiles
// of 128 columns. 4 warps, warp tile 32x64, mma.m16n8k16 bf16.
// Smem: A 132096 + B 4*18432=73728 + scratch 7424 = 213248 bytes.
#define SMEM_BYTES (BM * LDA_S * 2 + 4 * BN * LDB_S * 2 + 1856 * 4)

__global__ __launch_bounds__(NTHREADS, 1) void gemm_stats_kernel() {
    extern __shared__ char smem_raw[];
    __nv_bfloat16* As = (__nv_bfloat16*)smem_raw;
    __nv_bfloat16* Bs = As + BM * LDA_S;
    float* sp  = (float*)(Bs + 4 * BN * LDB_S);
    float* p_m = sp;          // [2][64]  row partials per wn
    float* p_s = sp + 128;
    float* p_v = sp + 256;
    float* p_d = sp + 384;
    float* c_m = sp + 512;    // [2][128] col partials per wm
    float* c_s = sp + 768;
    float* c_v = sp + 1024;
    float* c_d = sp + 1280;
    float* r_m = sp + 1536;   // [64] running row stats
    float* r_s = sp + 1600;
    float* r_v = sp + 1664;
    float* r_d = sp + 1728;
    float* red = sp + 1792;   // [64]

    const int tid  = threadIdx.x;
    const int lane = tid & 31;
    const int wid  = tid >> 5;
    const int wm   = wid >> 1;   // 0..1 (row half)
    const int wn   = wid & 1;    // 0..1 (col half)
    const int i0   = blockIdx.x * BM;

    // --- load resident A block [64 x 1024] bf16, padded stride ---
    {
        const __nv_bfloat16* gsrc = g_a + (size_t)i0 * ND;
        for (int c = tid; c < BM * (ND / 8); c += NTHREADS) {
            int row = c >> 7;              // 128 16B-chunks per row
            int col = (c & 127) * 8;
            *(uint4*)(As + row * LDA_S + col) =
                *(const uint4*)(gsrc + (size_t)row * ND + col);
        }
    }
    if (tid < BM) {
        r_m[tid] = -INFINITY; r_s[tid] = 0.f;
        r_v[tid] = -INFINITY; r_d[tid] = -INFINITY;
    }
    __syncthreads();

    const uint32_t sA = (uint32_t)__cvta_generic_to_shared(As);
    const uint32_t sB = (uint32_t)__cvta_generic_to_shared(Bs);
    const uint32_t bufBytes = BN * LDB_S * 2;   // 18432

    for (int jt = 0; jt < NJT; ++jt) {
        const int j0 = jt * BN;

        // --- prologue: prefetch k-chunks 0 and 1 ---
        #pragma unroll
        for (int pc = 0; pc < 2; ++pc) {
            const __nv_bfloat16* src0 = g_b + (size_t)j0 * ND + pc * BK;
            uint32_t bofs = (uint32_t)pc * bufBytes;
            for (int c = tid; c < BN * (BK / 8); c += NTHREADS) {
                int n = c >> 3; int cofs = (c & 7) * 8;
                uint32_t dst = sB + bofs + (uint32_t)((n * LDB_S + cofs) * 2);
                const __nv_bfloat16* src = src0 + (size_t)n * ND + cofs;
                asm volatile("cp.async.cg.shared.global [%0], [%1], 16;\n" ::"r"(dst), "l"(src));
            }
            asm volatile("cp.async.commit_group;\n");
        }

        float ac[2][8][4];
        #pragma unroll
        for (int a = 0; a < 2; a++)
            #pragma unroll
            for (int b = 0; b < 8; b++)
                #pragma unroll
                for (int e = 0; e < 4; e++) ac[a][b][e] = 0.f;

        for (int kc = 0; kc < NKC; ++kc) {
            if (kc + 2 < NKC) {
                const __nv_bfloat16* src0 = g_b + (size_t)j0 * ND + (kc + 2) * BK;
                uint32_t bofs = (uint32_t)((kc + 2) & 3) * bufBytes;
                for (int c = tid; c < BN * (BK / 8); c += NTHREADS) {
                    int n = c >> 3; int cofs = (c & 7) * 8;
                    uint32_t dst = sB + bofs + (uint32_t)((n * LDB_S + cofs) * 2);
                    const __nv_bfloat16* src = src0 + (size_t)n * ND + cofs;
                    asm volatile("cp.async.cg.shared.global [%0], [%1], 16;\n" ::"r"(dst), "l"(src));
                }
                asm volatile("cp.async.commit_group;\n");
                asm volatile("cp.async.wait_group 2;\n");
            } else if (kc + 1 < NKC) {
                asm volatile("cp.async.wait_group 1;\n");
            } else {
                asm volatile("cp.async.wait_group 0;\n");
            }
            __syncthreads();

            uint32_t bB = sB + (uint32_t)(kc & 3) * bufBytes;
            #pragma unroll
            for (int ks = 0; ks < BK / 16; ++ks) {
                const int kcol = kc * BK + ks * 16;
                const int mat  = lane >> 3;
                uint32_t af[2][4];
                #pragma unroll
                for (int mf = 0; mf < 2; ++mf) {
                    int row = wm * 32 + mf * 16 + ((mat & 1) << 3) + (lane & 7);
                    int kof = (mat >> 1) << 3;
                    uint32_t addr = sA + (uint32_t)((row * LDA_S + kcol + kof) * 2);
                    asm volatile(
                        "ldmatrix.sync.aligned.m8n8.x4.shared.b16 {%0,%1,%2,%3}, [%4];\n"
                        : "=r"(af[mf][0]), "=r"(af[mf][1]), "=r"(af[mf][2]), "=r"(af[mf][3])
                        : "r"(addr));
                }
                uint32_t bfr[8][2];
                #pragma unroll
                for (int P = 0; P < 4; ++P) {
                    int nrow = wn * 64 + P * 16 + ((mat >> 1) << 3) + (lane & 7);
                    int kof  = (mat & 1) << 3;
                    uint32_t addr = bB + (uint32_t)((nrow * LDB_S + ks * 16 + kof) * 2);
                    asm volatile(
                        "ldmatrix.sync.aligned.m8n8.x4.shared.b16 {%0,%1,%2,%3}, [%4];\n"
                        : "=r"(bfr[2 * P][0]), "=r"(bfr[2 * P][1]),
                          "=r"(bfr[2 * P + 1][0]), "=r"(bfr[2 * P + 1][1])
                        : "r"(addr));
                }
                #pragma unroll
                for (int mf = 0; mf < 2; ++mf)
                    #pragma unroll
                    for (int nf = 0; nf < 8; ++nf) {
                        asm volatile(
                            "mma.sync.aligned.m16n8k16.row.col.f32.bf16.bf16.f32 "
                            "{%0,%1,%2,%3},{%4,%5,%6,%7},{%8,%9},{%0,%1,%2,%3};\n"
                            : "+f"(ac[mf][nf][0]), "+f"(ac[mf][nf][1]),
                              "+f"(ac[mf][nf][2]), "+f"(ac[mf][nf][3])
                            : "r"(af[mf][0]), "r"(af[mf][1]), "r"(af[mf][2]), "r"(af[mf][3]),
                              "r"(bfr[nf][0]), "r"(bfr[nf][1]));
                    }
            }
        }
        // last compute done; all cp.async groups drained (wait_group 0 at kc=15)

        // ==================== per-tile statistics epilogue ====================
        // --- row stats (i2s): per thread 4 rows x 16 values; reduce over 4-lane group
        #pragma unroll
        for (int mf = 0; mf < 2; ++mf) {
            #pragma unroll
            for (int q = 0; q < 2; ++q) {
                int rowl = wm * 32 + mf * 16 + q * 8 + (lane >> 2);
                int grow = i0 + rowl;
                float lm = -INFINITY, lv = -INFINITY, ld = -INFINITY;
                #pragma unroll
                for (int nf = 0; nf < 8; ++nf)
                    #pragma unroll
                    for (int e = 0; e < 2; ++e) {
                        float x = ac[mf][nf][q * 2 + e];
                        int gcol = j0 + wn * 64 + nf * 8 + ((lane & 3) << 1) + e;
                        lm = fmaxf(lm, x);
                        if (gcol == grow) ld = x; else lv = fmaxf(lv, x);
                    }
                #pragma unroll
                for (int o = 1; o < 4; o <<= 1) {
                    lm = fmaxf(lm, __shfl_xor_sync(0xffffffffu, lm, o));
                    lv = fmaxf(lv, __shfl_xor_sync(0xffffffffu, lv, o));
                    ld = fmaxf(ld, __shfl_xor_sync(0xffffffffu, ld, o));
                }
                float ls = 0.f;
                #pragma unroll
                for (int nf = 0; nf < 8; ++nf)
                    #pragma unroll
                    for (int e = 0; e < 2; ++e)
                        ls += __expf(ac[mf][nf][q * 2 + e] - lm);
                #pragma unroll
                for (int o = 1; o < 4; o <<= 1)
                    ls += __shfl_xor_sync(0xffffffffu, ls, o);
                if ((lane & 3) == 0) {
                    p_m[wn * 64 + rowl] = lm;
                    p_s[wn * 64 + rowl] = ls;
                    p_v[wn * 64 + rowl] = lv;
                    p_d[wn * 64 + rowl] = ld;
                }
            }
        }
        // --- col stats (s2i): per thread 16 cols x 4 values; reduce over 8 lanes
        #pragma unroll
        for (int nf = 0; nf < 8; ++nf) {
            #pragma unroll
            for (int e = 0; e < 2; ++e) {
                int coll = wn * 64 + nf * 8 + ((lane & 3) << 1) + e;
                int gcol = j0 + coll;
                float cm = -INFINITY, cv = -INFINITY, cd = -INFINITY;
                #pragma unroll
                for (int mf = 0; mf < 2; ++mf)
                    #pragma unroll
                    for (int q = 0; q < 2; ++q) {
                        float x = ac[mf][nf][q * 2 + e];
                        int grow = i0 + wm * 32 + mf * 16 + q * 8 + (lane >> 2);
                        cm = fmaxf(cm, x);
                        if (grow == gcol) cd = x; else cv = fmaxf(cv, x);
                    }
                #pragma unroll
                for (int o = 4; o < 32; o <<= 1) {
                    cm = fmaxf(cm, __shfl_xor_sync(0xffffffffu, cm, o));
                    cv = fmaxf(cv, __shfl_xor_sync(0xffffffffu, cv, o));
                    cd = fmaxf(cd, __shfl_xor_sync(0xffffffffu, cd, o));
                }
                float cs = 0.f;
                #pragma unroll
                for (int mf = 0; mf < 2; ++mf)
                    #pragma unroll
                    for (int q = 0; q < 2; ++q)
                        cs += __expf(ac[mf][nf][q * 2 + e] - cm);
                #pragma unroll
                for (int o = 4; o < 32; o <<= 1)
                    cs += __shfl_xor_sync(0xffffffffu, cs, o);
                if (lane < 4) {
                    c_m[wm * 128 + coll] = cm;
                    c_s[wm * 128 + coll] = cs;
                    c_v[wm * 128 + coll] = cv;
                    c_d[wm * 128 + coll] = cd;
                }
            }
        }
        __syncthreads();

        // --- merge partials ---
        if (tid < 64) {  // rows: merge wn halves into running online stats
            float m = r_m[tid], s = r_s[tid], v = r_v[tid], d = r_d[tid];
            #pragma unroll
            for (int h = 0; h < 2; ++h) {
                float lm = p_m[h * 64 + tid], ls = p_s[h * 64 + tid];
                float nm = fmaxf(m, lm);
                s = s * __expf(m - nm) + ls * __expf(lm - nm);
                m = nm;
                v = fmaxf(v, p_v[h * 64 + tid]);
                d = fmaxf(d, p_d[h * 64 + tid]);
            }
            r_m[tid] = m; r_s[tid] = s; r_v[tid] = v; r_d[tid] = d;
        }
        {   // cols: merge wm halves, write global partials
            float m = c_m[tid], s = c_s[tid], v = c_v[tid], d = c_d[tid];
            float lm = c_m[128 + tid], ls = c_s[128 + tid];
            float nm = fmaxf(m, lm);
            s = s * __expf(m - nm) + ls * __expf(lm - nm);
            m = nm;
            v = fmaxf(v, c_v[128 + tid]);
            d = fmaxf(d, c_d[128 + tid]);
            size_t gi = (size_t)blockIdx.x * NB + j0 + tid;
            g_pm[gi] = m; g_ps[gi] = s; g_pv[gi] = v; g_pd[gi] = d;
        }
        __syncthreads();
    }

    // --- finalize row losses for this block ---
    if (tid < 64) {
        float m = r_m[tid], s = r_s[tid], v = r_v[tid], d = r_d[tid];
        float hv = HNW * v;
        float M2 = fmaxf(m, hv);
        float S  = s * __expf(m - M2) - __expf(v - M2) + __expf(hv - M2);
        red[tid] = (M2 + logf(S)) - d;
    }
    __syncthreads();
    if (tid == 0) {
        float sum = 0.f;
        #pragma unroll 8
        for (int i = 0; i < 64; ++i) sum += red[i];
        atomicAdd(&g_acc[0], (double)sum);
    }
}

// ----------------------------------------------------------------------------
__global__ void col_merge_kernel() {
    __shared__ float red[256];
    int c = blockIdx.x * blockDim.x + threadIdx.x;   // 0..8191
    float m = -INFINITY, s = 0.f, v = -INFINITY, d = -INFINITY;
    for (int b = 0; b < NBLK; ++b) {
        size_t gi = (size_t)b * NB + c;
        float lm = g_pm[gi], ls = g_ps[gi];
        float nm = fmaxf(m, lm);
        s = s * __expf(m - nm) + ls * __expf(lm - nm);
        m = nm;
        v = fmaxf(v, g_pv[gi]);
        d = fmaxf(d, g_pd[gi]);
    }
    float hv = HNW * v;
    float M2 = fmaxf(m, hv);
    float S  = s * __expf(m - M2) - __expf(v - M2) + __expf(hv - M2);
    red[threadIdx.x] = (M2 + logf(S)) - d;
    __syncthreads();
    if (threadIdx.x == 0) {
        float sum = 0.f;
        #pragma unroll 8
        for (int i = 0; i < 256; ++i) sum += red[i];
        atomicAdd(&g_acc[1], (double)sum);
    }
}

// ----------------------------------------------------------------------------
__global__ void finalize_kernel(float* out) {
    out[0] = (float)((g_acc[0] + g_acc[1]) * (0.5 / (double)NB));
}

// ----------------------------------------------------------------------------
extern "C" void kernel_launch(void* const* d_in, const int* in_sizes, int n_in,
                              void* d_out, int out_size) {
    const float* img  = (const float*)d_in[0];
    const float* song = (const float*)d_in[1];
    float* out = (float*)d_out;

    cudaFuncSetAttribute(gemm_stats_kernel,
                         cudaFuncAttributeMaxDynamicSharedMemorySize, SMEM_BYTES);

    convert_kernel<<<(NB * ND / 4 + 255) / 256, 256>>>(img, song);
    gemm_stats_kernel<<<NBLK, NTHREADS, SMEM_BYTES>>>();
    col_merge_kernel<<<NB / 256, 256>>>();
    finalize_kernel<<<1, 1>>>(out);
}

// round 2
// speedup vs baseline: 1.0018x; 1.0018x over previous
#include <cuda_runtime.h>
#include <cuda_bf16.h>
#include <cstdint>
#include <math.h>

// ============================================================================
// NTXentLoss (B=8192, D=1024) — single-GEMM-sweep row+col softmax stats.
// loss = 0.5*(mean_rows(LSE'_row - diag) + mean_cols(LSE'_col - diag))
// LSE' corrects for scaling the hard-negative (off-diag max) logit by 1.5.
// ============================================================================

#define NB 8192
#define ND 1024
#define BM 64
#define BN 128
#define BK 64
#define NTHREADS 128
#define LDA_S (ND + 8)   // 1032 elements: +16B/row to dodge ldmatrix conflicts
#define LDB_S (BK + 8)   // 72
#define NJT (NB / BN)    // 64 j-tiles
#define NKC (ND / BK)    // 16 k-chunks
#define NBLK (NB / BM)   // 128 blocks
#define TEMP_INV 20.0f   // 1/0.05, folded into image at conversion
#define HNW 1.5f         // 1 + hard_negative_weight

// Static device scratch (allocation-free rule)
__device__ __nv_bfloat16 g_a[(size_t)NB * ND];  // image * 20  (bf16)
__device__ __nv_bfloat16 g_b[(size_t)NB * ND];  // song        (bf16)
__device__ float g_pm[(size_t)NBLK * NB];       // per-(block,col) partial max
__device__ float g_ps[(size_t)NBLK * NB];       // partial expsum
__device__ float g_pv[(size_t)NBLK * NB];       // partial offdiag max
__device__ float g_pd[(size_t)NBLK * NB];       // partial diag (-inf if absent)
__device__ double g_acc[2];                     // [0]=i2s row losses, [1]=s2i

// ----------------------------------------------------------------------------
__global__ void convert_kernel(const float* __restrict__ img,
                               const float* __restrict__ song) {
    size_t i = (size_t)blockIdx.x * blockDim.x + threadIdx.x;
    if (i == 0) { g_acc[0] = 0.0; g_acc[1] = 0.0; }
    size_t idx = i * 4;
    if (idx < (size_t)NB * ND) {
        float4 a = *(const float4*)(img + idx);
        float4 b = *(const float4*)(song + idx);
        *(__nv_bfloat162*)(g_a + idx)     = __floats2bfloat162_rn(a.x * TEMP_INV, a.y * TEMP_INV);
        *(__nv_bfloat162*)(g_a + idx + 2) = __floats2bfloat162_rn(a.z * TEMP_INV, a.w * TEMP_INV);
        *(__nv_bfloat162*)(g_b + idx)     = __floats2bfloat162_rn(b.x, b.y);
        *(__nv_bfloat162*)(g_b + idx + 2) = __floats2bfloat162_rn(b.z, b.w);
    }
}

// ----------------------------------------------------------------------------
// GEMM + stats: block = 64 rows (A resident in smem, full K), sweeps 64 tiles
// of 128 columns. 4 warps, warp tile 32x64, mma.m16n8k16 bf16.
// Smem: A 132096 + B 4*18432=73728 + scratch 7424 = 213248 bytes.
#define SMEM_BYTES (BM * LDA_S * 2 + 4 * BN * LDB_S * 2 + 1856 * 4)

__global__ __launch_bounds__(NTHREADS, 1) void gemm_stats_kernel() {
    extern __shared__ char smem_raw[];
    __nv_bfloat16* As = (__nv_bfloat16*)smem_raw;
    __nv_bfloat16* Bs = As + BM * LDA_S;
    float* sp  = (float*)(Bs + 4 * BN * LDB_S);
    float* p_m = sp;          // [2][64]  row partials per wn
    float* p_s = sp + 128;
    float* p_v = sp + 256;
    float* p_d = sp + 384;
    float* c_m = sp + 512;    // [2][128] col partials per wm
    float* c_s = sp + 768;
    float* c_v = sp + 1024;
    float* c_d = sp + 1280;
    float* r_m = sp + 1536;   // [64] running row stats
    float* r_s = sp + 1600;
    float* r_v = sp + 1664;
    float* r_d = sp + 1728;
    float* red = sp + 1792;   // [64]

    const int tid  = threadIdx.x;
    const int lane = tid & 31;
    const int wid  = tid >> 5;
    const int wm   = wid >> 1;   // 0..1 (row half)
    const int wn   = wid & 1;    // 0..1 (col half)
    const int i0   = blockIdx.x * BM;

    // --- load resident A block [64 x 1024] bf16, padded stride ---
    {
        const __nv_bfloat16* gsrc = g_a + (size_t)i0 * ND;
        for (int c = tid; c < BM * (ND / 8); c += NTHREADS) {
            int row = c >> 7;              // 128 16B-chunks per row
            int col = (c & 127) * 8;
            *(uint4*)(As + row * LDA_S + col) =
                *(const uint4*)(gsrc + (size_t)row * ND + col);
        }
    }
    if (tid < BM) {
        r_m[tid] = -INFINITY; r_s[tid] = 0.f;
        r_v[tid] = -INFINITY; r_d[tid] = -INFINITY;
    }
    __syncthreads();

    const uint32_t sA = (uint32_t)__cvta_generic_to_shared(As);
    const uint32_t sB = (uint32_t)__cvta_generic_to_shared(Bs);
    const uint32_t bufBytes = BN * LDB_S * 2;   // 18432

    for (int jt = 0; jt < NJT; ++jt) {
        const int j0 = jt * BN;

        // --- prologue: prefetch k-chunks 0 and 1 ---
        #pragma unroll
        for (int pc = 0; pc < 2; ++pc) {
            const __nv_bfloat16* src0 = g_b + (size_t)j0 * ND + pc * BK;
            uint32_t bofs = (uint32_t)pc * bufBytes;
            for (int c = tid; c < BN * (BK / 8); c += NTHREADS) {
                int n = c >> 3; int cofs = (c & 7) * 8;
                uint32_t dst = sB + bofs + (uint32_t)((n * LDB_S + cofs) * 2);
                const __nv_bfloat16* src = src0 + (size_t)n * ND + cofs;
                asm volatile("cp.async.cg.shared.global [%0], [%1], 16;\n" ::"r"(dst), "l"(src));
            }
            asm volatile("cp.async.commit_group;\n");
        }

        float ac[2][8][4];
        #pragma unroll
        for (int a = 0; a < 2; a++)
            #pragma unroll
            for (int b = 0; b < 8; b++)
                #pragma unroll
                for (int e = 0; e < 4; e++) ac[a][b][e] = 0.f;

        for (int kc = 0; kc < NKC; ++kc) {
            if (kc + 2 < NKC) {
                const __nv_bfloat16* src0 = g_b + (size_t)j0 * ND + (kc + 2) * BK;
                uint32_t bofs = (uint32_t)((kc + 2) & 3) * bufBytes;
                for (int c = tid; c < BN * (BK / 8); c += NTHREADS) {
                    int n = c >> 3; int cofs = (c & 7) * 8;
                    uint32_t dst = sB + bofs + (uint32_t)((n * LDB_S + cofs) * 2);
                    const __nv_bfloat16* src = src0 + (size_t)n * ND + cofs;
                    asm volatile("cp.async.cg.shared.global [%0], [%1], 16;\n" ::"r"(dst), "l"(src));
                }
                asm volatile("cp.async.commit_group;\n");
                asm volatile("cp.async.wait_group 2;\n");
            } else if (kc + 1 < NKC) {
                asm volatile("cp.async.wait_group 1;\n");
            } else {
                asm volatile("cp.async.wait_group 0;\n");
            }
            __syncthreads();

            uint32_t bB = sB + (uint32_t)(kc & 3) * bufBytes;
            #pragma unroll
            for (int ks = 0; ks < BK / 16; ++ks) {
                const int kcol = kc * BK + ks * 16;
                const int mat  = lane >> 3;
                uint32_t af[2][4];
                #pragma unroll
                for (int mf = 0; mf < 2; ++mf) {
                    int row = wm * 32 + mf * 16 + ((mat & 1) << 3) + (lane & 7);
                    int kof = (mat >> 1) << 3;
                    uint32_t addr = sA + (uint32_t)((row * LDA_S + kcol + kof) * 2);
                    asm volatile(
                        "ldmatrix.sync.aligned.m8n8.x4.shared.b16 {%0,%1,%2,%3}, [%4];\n"
                        : "=r"(af[mf][0]), "=r"(af[mf][1]), "=r"(af[mf][2]), "=r"(af[mf][3])
                        : "r"(addr));
                }
                uint32_t bfr[8][2];
                #pragma unroll
                for (int P = 0; P < 4; ++P) {
                    int nrow = wn * 64 + P * 16 + ((mat >> 1) << 3) + (lane & 7);
                    int kof  = (mat & 1) << 3;
                    uint32_t addr = bB + (uint32_t)((nrow * LDB_S + ks * 16 + kof) * 2);
                    asm volatile(
                        "ldmatrix.sync.aligned.m8n8.x4.shared.b16 {%0,%1,%2,%3}, [%4];\n"
                        : "=r"(bfr[2 * P][0]), "=r"(bfr[2 * P][1]),
                          "=r"(bfr[2 * P + 1][0]), "=r"(bfr[2 * P + 1][1])
                        : "r"(addr));
                }
                #pragma unroll
                for (int mf = 0; mf < 2; ++mf)
                    #pragma unroll
                    for (int nf = 0; nf < 8; ++nf) {
                        asm volatile(
                            "mma.sync.aligned.m16n8k16.row.col.f32.bf16.bf16.f32 "
                            "{%0,%1,%2,%3},{%4,%5,%6,%7},{%8,%9},{%0,%1,%2,%3};\n"
                            : "+f"(ac[mf][nf][0]), "+f"(ac[mf][nf][1]),
                              "+f"(ac[mf][nf][2]), "+f"(ac[mf][nf][3])
                            : "r"(af[mf][0]), "r"(af[mf][1]), "r"(af[mf][2]), "r"(af[mf][3]),
                              "r"(bfr[nf][0]), "r"(bfr[nf][1]));
                    }
            }
        }
        // last compute done; all cp.async groups drained (wait_group 0 at kc=15)

        // ==================== per-tile statistics epilogue ====================
        // --- row stats (i2s): per thread 4 rows x 16 values; reduce over 4-lane group
        #pragma unroll
        for (int mf = 0; mf < 2; ++mf) {
            #pragma unroll
            for (int q = 0; q < 2; ++q) {
                int rowl = wm * 32 + mf * 16 + q * 8 + (lane >> 2);
                int grow = i0 + rowl;
                float lm = -INFINITY, lv = -INFINITY, ld = -INFINITY;
                #pragma unroll
                for (int nf = 0; nf < 8; ++nf)
                    #pragma unroll
                    for (int e = 0; e < 2; ++e) {
                        float x = ac[mf][nf][q * 2 + e];
                        int gcol = j0 + wn * 64 + nf * 8 + ((lane & 3) << 1) + e;
                        lm = fmaxf(lm, x);
                        if (gcol == grow) ld = x; else lv = fmaxf(lv, x);
                    }
                #pragma unroll
                for (int o = 1; o < 4; o <<= 1) {
                    lm = fmaxf(lm, __shfl_xor_sync(0xffffffffu, lm, o));
                    lv = fmaxf(lv, __shfl_xor_sync(0xffffffffu, lv, o));
                    ld = fmaxf(ld, __shfl_xor_sync(0xffffffffu, ld, o));
                }
                float ls = 0.f;
                #pragma unroll
                for (int nf = 0; nf < 8; ++nf)
                    #pragma unroll
                    for (int e = 0; e < 2; ++e)
                        ls += __expf(ac[mf][nf][q * 2 + e] - lm);
                #pragma unroll
                for (int o = 1; o < 4; o <<= 1)
                    ls += __shfl_xor_sync(0xffffffffu, ls, o);
                if ((lane & 3) == 0) {
                    p_m[wn * 64 + rowl] = lm;
                    p_s[wn * 64 + rowl] = ls;
                    p_v[wn * 64 + rowl] = lv;
                    p_d[wn * 64 + rowl] = ld;
                }
            }
        }
        // --- col stats (s2i): per thread 16 cols x 4 values; reduce over 8 lanes
        #pragma unroll
        for (int nf = 0; nf < 8; ++nf) {
            #pragma unroll
            for (int e = 0; e < 2; ++e) {
                int coll = wn * 64 + nf * 8 + ((lane & 3) << 1) + e;
                int gcol = j0 + coll;
                float cm = -INFINITY, cv = -INFINITY, cd = -INFINITY;
                #pragma unroll
                for (int mf = 0; mf < 2; ++mf)
                    #pragma unroll
                    for (int q = 0; q < 2; ++q) {
                        float x = ac[mf][nf][q * 2 + e];
                        int grow = i0 + wm * 32 + mf * 16 + q * 8 + (lane >> 2);
                        cm = fmaxf(cm, x);
                        if (grow == gcol) cd = x; else cv = fmaxf(cv, x);
                    }
                #pragma unroll
                for (int o = 4; o < 32; o <<= 1) {
                    cm = fmaxf(cm, __shfl_xor_sync(0xffffffffu, cm, o));
                    cv = fmaxf(cv, __shfl_xor_sync(0xffffffffu, cv, o));
                    cd = fmaxf(cd, __shfl_xor_sync(0xffffffffu, cd, o));
                }
                float cs = 0.f;
                #pragma unroll
                for (int mf = 0; mf < 2; ++mf)
                    #pragma unroll
                    for (int q = 0; q < 2; ++q)
                        cs += __expf(ac[mf][nf][q * 2 + e] - cm);
                #pragma unroll
                for (int o = 4; o < 32; o <<= 1)
                    cs += __shfl_xor_sync(0xffffffffu, cs, o);
                if (lane < 4) {
                    c_m[wm * 128 + coll] = cm;
                    c_s[wm * 128 + coll] = cs;
                    c_v[wm * 128 + coll] = cv;
                    c_d[wm * 128 + coll] = cd;
                }
            }
        }
        __syncthreads();

        // --- merge partials ---
        if (tid < 64) {  // rows: merge wn halves into running online stats
            float m = r_m[tid], s = r_s[tid], v = r_v[tid], d = r_d[tid];
            #pragma unroll
            for (int h = 0; h < 2; ++h) {
                float lm = p_m[h * 64 + tid], ls = p_s[h * 64 + tid];
                float nm = fmaxf(m, lm);
                s = s * __expf(m - nm) + ls * __expf(lm - nm);
                m = nm;
                v = fmaxf(v, p_v[h * 64 + tid]);
                d = fmaxf(d, p_d[h * 64 + tid]);
            }
            r_m[tid] = m; r_s[tid] = s; r_v[tid] = v; r_d[tid] = d;
        }
        {   // cols: merge wm halves, write global partials
            float m = c_m[tid], s = c_s[tid], v = c_v[tid], d = c_d[tid];
            float lm = c_m[128 + tid], ls = c_s[128 + tid];
            float nm = fmaxf(m, lm);
            s = s * __expf(m - nm) + ls * __expf(lm - nm);
            m = nm;
            v = fmaxf(v, c_v[128 + tid]);
            d = fmaxf(d, c_d[128 + tid]);
            size_t gi = (size_t)blockIdx.x * NB + j0 + tid;
            g_pm[gi] = m; g_ps[gi] = s; g_pv[gi] = v; g_pd[gi] = d;
        }
        __syncthreads();
    }

    // --- finalize row losses for this block ---
    if (tid < 64) {
        float m = r_m[tid], s = r_s[tid], v = r_v[tid], d = r_d[tid];
        float hv = HNW * v;
        float M2 = fmaxf(m, hv);
        float S  = s * __expf(m - M2) - __expf(v - M2) + __expf(hv - M2);
        red[tid] = (M2 + logf(S)) - d;
    }
    __syncthreads();
    if (tid == 0) {
        float sum = 0.f;
        #pragma unroll 8
        for (int i = 0; i < 64; ++i) sum += red[i];
        atomicAdd(&g_acc[0], (double)sum);
    }
}

// ----------------------------------------------------------------------------
__global__ void col_merge_kernel() {
    __shared__ float red[256];
    int c = blockIdx.x * blockDim.x + threadIdx.x;   // 0..8191
    float m = -INFINITY, s = 0.f, v = -INFINITY, d = -INFINITY;
    for (int b = 0; b < NBLK; ++b) {
        size_t gi = (size_t)b * NB + c;
        float lm = g_pm[gi], ls = g_ps[gi];
        float nm = fmaxf(m, lm);
        s = s * __expf(m - nm) + ls * __expf(lm - nm);
        m = nm;
        v = fmaxf(v, g_pv[gi]);
        d = fmaxf(d, g_pd[gi]);
    }
    float hv = HNW * v;
    float M2 = fmaxf(m, hv);
    float S  = s * __expf(m - M2) - __expf(v - M2) + __expf(hv - M2);
    red[threadIdx.x] = (M2 + logf(S)) - d;
    __syncthreads();
    if (threadIdx.x == 0) {
        float sum = 0.f;
        #pragma unroll 8
        for (int i = 0; i < 256; ++i) sum += red[i];
        atomicAdd(&g_acc[1], (double)sum);
    }
}

// ----------------------------------------------------------------------------
__global__ void finalize_kernel(float* out) {
    out[0] = (float)((g_acc[0] + g_acc[1]) * (0.5 / (double)NB));
}

// ----------------------------------------------------------------------------
extern "C" void kernel_launch(void* const* d_in, const int* in_sizes, int n_in,
                              void* d_out, int out_size) {
    const float* img  = (const float*)d_in[0];
    const float* song = (const float*)d_in[1];
    float* out = (float*)d_out;

    cudaFuncSetAttribute(gemm_stats_kernel,
                         cudaFuncAttributeMaxDynamicSharedMemorySize, SMEM_BYTES);

    convert_kernel<<<(NB * ND / 4 + 255) / 256, 256>>>(img, song);
    gemm_stats_kernel<<<NBLK, NTHREADS, SMEM_BYTES>>>();
    col_merge_kernel<<<NB / 256, 256>>>();
    finalize_kernel<<<1, 1>>>(out);
}